// round 3
// baseline (speedup 1.0000x reference)
#include <cuda_runtime.h>

#define Cdim 768
#define CRdim 192
#define Bb 8
#define Nn 1024

// Scratch: gc | vbar_acc | ca_acc | ybar_acc | h_acc | dummy(warm sinks)
#define S_GC 0
#define S_VB (Bb * Cdim)
#define S_CA (2 * Bb * Cdim)
#define S_YB (3 * Bb * Cdim)
#define S_H  (4 * Bb * Cdim)
#define S_DUM (4 * Bb * Cdim + Bb * CRdim)
__device__ __align__(16) float g_scr[S_DUM + 64];

// K1: gc[b,c] = mean_n x[b,n,c]  (blocks 0..127, float4, 192 thr)
//     + weight warm into L2      (blocks 128..187)
__global__ void __launch_bounds__(192) k_gc(const float* __restrict__ x,
                                            const float* __restrict__ Wv,
                                            const float* __restrict__ W1,
                                            const float* __restrict__ W2,
                                            const float* __restrict__ Wo) {
    int t = threadIdx.x;
    if (blockIdx.x < 128) {
        int b = blockIdx.x >> 4;
        int chunk = blockIdx.x & 15;
        const float4* p = reinterpret_cast<const float4*>(x)
                        + ((size_t)(b * Nn + chunk * 64) * Cdim) / 4 + t;
        float4 s = make_float4(0.f, 0.f, 0.f, 0.f);
        #pragma unroll 8
        for (int n = 0; n < 64; n++) {
            float4 v = p[(size_t)n * (Cdim / 4)];
            s.x += v.x; s.y += v.y; s.z += v.z; s.w += v.w;
        }
        float* g = &g_scr[S_GC + b * Cdim + 4 * t];
        const float inv = 1.0f / Nn;
        atomicAdd(g + 0, s.x * inv);
        atomicAdd(g + 1, s.y * inv);
        atomicAdd(g + 2, s.z * inv);
        atomicAdd(g + 3, s.w * inv);
    } else {
        // Warm 6MB of weights into L2. Each block: 6144 float4 (96KB).
        int wb = blockIdx.x - 128;
        const float4* base; int part;
        if (wb < 24)      { base = (const float4*)Wv; part = wb; }
        else if (wb < 30) { base = (const float4*)W1; part = wb - 24; }
        else if (wb < 54) { base = (const float4*)Wo; part = wb - 30; }
        else              { base = (const float4*)W2; part = wb - 54; }
        const float4* p = base + (size_t)part * 6144 + t;
        float4 s = make_float4(0.f, 0.f, 0.f, 0.f);
        #pragma unroll 8
        for (int i = 0; i < 32; i++) {
            float4 v = p[(size_t)i * 192];
            s.x += v.x; s.y += v.y; s.z += v.z; s.w += v.w;
        }
        if (t == 0) g_scr[S_DUM + wb] = s.x + s.y + s.z + s.w;
    }
}

// K2: vbar = gc@Wv (col-quads 0..191), h = gc@W1 (quads 192..239).
// 256 thr = 64 quads x 4 k-lanes; K-tile 64 (16 k per lane), float4 weights.
// grid (4, 12)
__global__ void __launch_bounds__(256) k_gemm1(const float* __restrict__ Wv,
                                               const float* __restrict__ W1) {
    __shared__ float sg[Bb][64];
    int t = threadIdx.x;
    int k0 = blockIdx.y * 64;
    for (int i = t; i < Bb * 64; i += 256)
        sg[i >> 6][i & 63] = g_scr[S_GC + (i >> 6) * Cdim + k0 + (i & 63)];
    __syncthreads();
    int q = t >> 2, kg = t & 3;
    int Q = blockIdx.x * 64 + q;
    bool valid = Q < 240;
    float acc[Bb][4];
    #pragma unroll
    for (int b = 0; b < Bb; b++) { acc[b][0]=0.f; acc[b][1]=0.f; acc[b][2]=0.f; acc[b][3]=0.f; }
    int kbase = k0 + kg * 16;
    if (valid) {
        if (Q < 192) {
            const float4* wp = (const float4*)Wv + (size_t)kbase * 192 + Q;
            #pragma unroll
            for (int kk = 0; kk < 16; kk++) {
                float4 w = wp[(size_t)kk * 192];
                int ki = kg * 16 + kk;
                #pragma unroll
                for (int b = 0; b < Bb; b++) {
                    float a = sg[b][ki];
                    acc[b][0] += a * w.x; acc[b][1] += a * w.y;
                    acc[b][2] += a * w.z; acc[b][3] += a * w.w;
                }
            }
        } else {
            const float4* wp = (const float4*)W1 + (size_t)kbase * 48 + (Q - 192);
            #pragma unroll
            for (int kk = 0; kk < 16; kk++) {
                float4 w = wp[(size_t)kk * 48];
                int ki = kg * 16 + kk;
                #pragma unroll
                for (int b = 0; b < Bb; b++) {
                    float a = sg[b][ki];
                    acc[b][0] += a * w.x; acc[b][1] += a * w.y;
                    acc[b][2] += a * w.z; acc[b][3] += a * w.w;
                }
            }
        }
    }
    #pragma unroll
    for (int b = 0; b < Bb; b++)
        #pragma unroll
        for (int j = 0; j < 4; j++) {
            acc[b][j] += __shfl_xor_sync(0xffffffffu, acc[b][j], 1);
            acc[b][j] += __shfl_xor_sync(0xffffffffu, acc[b][j], 2);
        }
    if (valid && kg == 0) {
        if (Q < 192) {
            #pragma unroll
            for (int b = 0; b < Bb; b++)
                #pragma unroll
                for (int j = 0; j < 4; j++)
                    atomicAdd(&g_scr[S_VB + b * Cdim + 4 * Q + j], acc[b][j]);
        } else {
            #pragma unroll
            for (int b = 0; b < Bb; b++)
                #pragma unroll
                for (int j = 0; j < 4; j++)
                    atomicAdd(&g_scr[S_H + b * CRdim + 4 * (Q - 192) + j], acc[b][j]);
        }
    }
}

// K3: ca_pre = relu(h + b1) @ W2.  grid (3, 3), K-tile 64 over K=192.
__global__ void __launch_bounds__(256) k_gemm2(const float* __restrict__ W2,
                                               const float* __restrict__ b1) {
    __shared__ float sh[Bb][64];
    int t = threadIdx.x;
    int k0 = blockIdx.y * 64;
    for (int i = t; i < Bb * 64; i += 256) {
        int b = i >> 6, kk = i & 63;
        float v = g_scr[S_H + b * CRdim + k0 + kk] + b1[k0 + kk];
        sh[b][kk] = v > 0.f ? v : 0.f;
    }
    __syncthreads();
    int q = t >> 2, kg = t & 3;
    int Q = blockIdx.x * 64 + q;
    float acc[Bb][4];
    #pragma unroll
    for (int b = 0; b < Bb; b++) { acc[b][0]=0.f; acc[b][1]=0.f; acc[b][2]=0.f; acc[b][3]=0.f; }
    const float4* wp = (const float4*)W2 + (size_t)(k0 + kg * 16) * 192 + Q;
    #pragma unroll
    for (int kk = 0; kk < 16; kk++) {
        float4 w = wp[(size_t)kk * 192];
        int ki = kg * 16 + kk;
        #pragma unroll
        for (int b = 0; b < Bb; b++) {
            float a = sh[b][ki];
            acc[b][0] += a * w.x; acc[b][1] += a * w.y;
            acc[b][2] += a * w.z; acc[b][3] += a * w.w;
        }
    }
    #pragma unroll
    for (int b = 0; b < Bb; b++)
        #pragma unroll
        for (int j = 0; j < 4; j++) {
            acc[b][j] += __shfl_xor_sync(0xffffffffu, acc[b][j], 1);
            acc[b][j] += __shfl_xor_sync(0xffffffffu, acc[b][j], 2);
        }
    if (kg == 0) {
        #pragma unroll
        for (int b = 0; b < Bb; b++)
            #pragma unroll
            for (int j = 0; j < 4; j++)
                atomicAdd(&g_scr[S_CA + b * Cdim + 4 * Q + j], acc[b][j]);
    }
}

// K4: ybar = ((vbar+bv) * sigmoid(ca+b2)) @ Wo.  grid (3, 12).
__global__ void __launch_bounds__(256) k_gemm3(const float* __restrict__ Wo,
                                               const float* __restrict__ bv,
                                               const float* __restrict__ b2) {
    __shared__ float sy[Bb][64];
    int t = threadIdx.x;
    int k0 = blockIdx.y * 64;
    for (int i = t; i < Bb * 64; i += 256) {
        int b = i >> 6, kk = i & 63;
        int k = k0 + kk;
        float vb = g_scr[S_VB + b * Cdim + k] + bv[k];
        float cp = g_scr[S_CA + b * Cdim + k] + b2[k];
        sy[b][kk] = vb * (1.f / (1.f + __expf(-cp)));
    }
    __syncthreads();
    int q = t >> 2, kg = t & 3;
    int Q = blockIdx.x * 64 + q;
    float acc[Bb][4];
    #pragma unroll
    for (int b = 0; b < Bb; b++) { acc[b][0]=0.f; acc[b][1]=0.f; acc[b][2]=0.f; acc[b][3]=0.f; }
    const float4* wp = (const float4*)Wo + (size_t)(k0 + kg * 16) * 192 + Q;
    #pragma unroll
    for (int kk = 0; kk < 16; kk++) {
        float4 w = wp[(size_t)kk * 192];
        int ki = kg * 16 + kk;
        #pragma unroll
        for (int b = 0; b < Bb; b++) {
            float a = sy[b][ki];
            acc[b][0] += a * w.x; acc[b][1] += a * w.y;
            acc[b][2] += a * w.z; acc[b][3] += a * w.w;
        }
    }
    #pragma unroll
    for (int b = 0; b < Bb; b++)
        #pragma unroll
        for (int j = 0; j < 4; j++) {
            acc[b][j] += __shfl_xor_sync(0xffffffffu, acc[b][j], 1);
            acc[b][j] += __shfl_xor_sync(0xffffffffu, acc[b][j], 2);
        }
    if (kg == 0) {
        #pragma unroll
        for (int b = 0; b < Bb; b++)
            #pragma unroll
            for (int j = 0; j < 4; j++)
                atomicAdd(&g_scr[S_YB + b * Cdim + 4 * Q + j], acc[b][j]);
    }
}

// K5: out[row,:] = LN(x[row,:] + ybar[b,:] + bo) * gamma + beta.
__global__ void __launch_bounds__(192) k_ln(const float* __restrict__ x,
                                            const float* __restrict__ bo,
                                            const float* __restrict__ gamma,
                                            const float* __restrict__ beta,
                                            float* __restrict__ out) {
    __shared__ float red[2][8];
    int row = blockIdx.x;
    int b = row >> 10;
    int t = threadIdx.x;
    float4 xv = reinterpret_cast<const float4*>(x + (size_t)row * Cdim)[t];
    float4 yv = reinterpret_cast<const float4*>(&g_scr[S_YB + b * Cdim])[t];
    float4 bo4 = reinterpret_cast<const float4*>(bo)[t];
    float v0 = xv.x + yv.x + bo4.x;
    float v1 = xv.y + yv.y + bo4.y;
    float v2 = xv.z + yv.z + bo4.z;
    float v3 = xv.w + yv.w + bo4.w;
    float s = v0 + v1 + v2 + v3;
    float q = v0 * v0 + v1 * v1 + v2 * v2 + v3 * v3;
    #pragma unroll
    for (int o = 16; o; o >>= 1) {
        s += __shfl_xor_sync(0xffffffff, s, o);
        q += __shfl_xor_sync(0xffffffff, q, o);
    }
    int w = t >> 5;
    if ((t & 31) == 0) { red[0][w] = s; red[1][w] = q; }
    __syncthreads();
    if (t < 32) {
        float ss = (t < 6) ? red[0][t] : 0.f;
        float qq = (t < 6) ? red[1][t] : 0.f;
        #pragma unroll
        for (int o = 4; o; o >>= 1) {
            ss += __shfl_xor_sync(0xffffffff, ss, o);
            qq += __shfl_xor_sync(0xffffffff, qq, o);
        }
        if (t == 0) { red[0][0] = ss; red[1][0] = qq; }
    }
    __syncthreads();
    float mean = red[0][0] * (1.0f / Cdim);
    float var = red[1][0] * (1.0f / Cdim) - mean * mean;
    float rstd = rsqrtf(var + 1e-5f);
    float4 g4 = reinterpret_cast<const float4*>(gamma)[t];
    float4 be4 = reinterpret_cast<const float4*>(beta)[t];
    float4 o4;
    o4.x = (v0 - mean) * rstd * g4.x + be4.x;
    o4.y = (v1 - mean) * rstd * g4.y + be4.y;
    o4.z = (v2 - mean) * rstd * g4.z + be4.z;
    o4.w = (v3 - mean) * rstd * g4.w + be4.w;
    reinterpret_cast<float4*>(out + (size_t)row * Cdim)[t] = o4;
}

extern "C" void kernel_launch(void* const* d_in, const int* in_sizes, int n_in,
                              void* d_out, int out_size) {
    const float* x     = (const float*)d_in[0];
    // d_in[1..4] = Wq, bq, Wk, bk — mathematically unused (softmax over a
    // constant-in-m score row is exactly uniform -> attention out = mean of v
    // = gc@Wv+bv, independent of q/k).
    const float* Wv    = (const float*)d_in[5];
    const float* bv    = (const float*)d_in[6];
    const float* W1    = (const float*)d_in[7];
    const float* b1    = (const float*)d_in[8];
    const float* W2    = (const float*)d_in[9];
    const float* b2    = (const float*)d_in[10];
    const float* Wo    = (const float*)d_in[11];
    const float* bo    = (const float*)d_in[12];
    const float* gamma = (const float*)d_in[13];
    const float* beta  = (const float*)d_in[14];
    float* out = (float*)d_out;

    void* scr = nullptr;
    cudaGetSymbolAddress(&scr, g_scr);
    cudaMemsetAsync(scr, 0, sizeof(float) * (S_DUM + 64), 0);

    k_gc<<<188, 192>>>(x, Wv, W1, W2, Wo);
    k_gemm1<<<dim3(4, 12), 256>>>(Wv, W1);
    k_gemm2<<<dim3(3, 3), 256>>>(W2, b1);
    k_gemm3<<<dim3(3, 12), 256>>>(Wo, bv, b2);
    k_ln<<<Bb * Nn, 192>>>(x, bo, gamma, beta, out);
}

// round 4
// speedup vs baseline: 1.1067x; 1.1067x over previous
#include <cuda_runtime.h>

#define Cdim 768
#define CRdim 192
#define Bb 8
#define Nn 1024

// Scratch layout (floats):
//  S_VB[8*768] | S_CA[8*768] | S_YB[8*768] | S_H[8*192] | S_GCP[8*16*768]
#define S_VB  0
#define S_CA  (Bb * Cdim)
#define S_YB  (2 * Bb * Cdim)
#define S_H   (3 * Bb * Cdim)
#define S_ZERO_END (3 * Bb * Cdim + Bb * CRdim)
#define S_GCP S_ZERO_END
#define S_TOTAL (S_ZERO_END + Bb * 16 * Cdim)
__device__ __align__(16) float g_scr[S_TOTAL];
__device__ unsigned int g_bar[4];   // [0]=cnt0 [1]=flag0 [2]=cnt1 [3]=flag1

// ───────────────────────── K1: gc partials + zero accumulators ─────────────
// blocks 0..127: partial sums of x over 64-row chunks (race-free writes).
// blocks 128..135: zero the GEMM accumulators and barrier state.
__global__ void __launch_bounds__(192) k_gc(const float* __restrict__ x) {
    int t = threadIdx.x;
    if (blockIdx.x < 128) {
        int b = blockIdx.x >> 4;
        int chunk = blockIdx.x & 15;
        const float4* p = reinterpret_cast<const float4*>(x)
                        + (size_t)(b * Nn + chunk * 64) * (Cdim / 4) + t;
        float4 s = make_float4(0.f, 0.f, 0.f, 0.f);
        #pragma unroll 8
        for (int n = 0; n < 64; n++) {
            float4 v = p[(size_t)n * (Cdim / 4)];
            s.x += v.x; s.y += v.y; s.z += v.z; s.w += v.w;
        }
        reinterpret_cast<float4*>(&g_scr[S_GCP + (size_t)(b * 16 + chunk) * Cdim])[t] = s;
    } else {
        int i = (blockIdx.x - 128) * 192 + t;
        for (; i < S_ZERO_END; i += 8 * 192) g_scr[i] = 0.f;
        if (blockIdx.x == 128 && t < 4) g_bar[t] = 0u;
    }
}

// ───────────────────────── grid barrier (all 60 blocks resident) ───────────
__device__ __forceinline__ void grid_bar(int slot, int nblocks) {
    __syncthreads();
    if (threadIdx.x == 0) {
        __threadfence();
        unsigned old = atomicAdd(&g_bar[2 * slot], 1u);
        if (old == (unsigned)(nblocks - 1)) {
            atomicExch(&g_bar[2 * slot + 1], 1u);
        } else {
            while (*((volatile unsigned int*)&g_bar[2 * slot + 1]) == 0u) { }
        }
        __threadfence();
    }
    __syncthreads();
}

// ───────────────────────── K2: fused GEMM chain ────────────────────────────
// grid 60 x 192 threads.  Thread = (quad q = t>>2, k-lane kg = t&3).
// Stage A (60 blk): vbar = gc@Wv, h = gc@W1        (atomic k-split partials)
// Stage B (12 blk): ca_pre = relu(h+b1)@W2
// Stage C (48 blk): ybar = ((vbar+bv)*sigmoid(ca+b2))@Wo
__global__ void __launch_bounds__(192) k_chain(const float* __restrict__ Wv,
                                               const float* __restrict__ W1,
                                               const float* __restrict__ W2,
                                               const float* __restrict__ Wo,
                                               const float* __restrict__ bv,
                                               const float* __restrict__ b1,
                                               const float* __restrict__ b2) {
    __shared__ float sa[Bb][64];
    int t = threadIdx.x;
    int q = t >> 2, kg = t & 3;

    // ---------------- Stage A ----------------
    {
        int ct = blockIdx.x / 12;          // 0..4  (col tile of 48 quads)
        int kt = blockIdx.x % 12;          // 0..11 (k tile of 64)
        int k0 = kt * 64;
        // build gc slice: sum 16 chunk partials, scale by 1/N
        for (int i = t; i < Bb * 64; i += 192) {
            int b = i >> 6, kk = i & 63;
            float s = 0.f;
            const float* pp = &g_scr[S_GCP + (size_t)(b * 16) * Cdim + k0 + kk];
            #pragma unroll
            for (int ch = 0; ch < 16; ch++) s += pp[(size_t)ch * Cdim];
            sa[b][kk] = s * (1.0f / Nn);
        }
        __syncthreads();
        int Q = ct * 48 + q;               // 0..239 col-quad
        float acc[Bb][4];
        #pragma unroll
        for (int b = 0; b < Bb; b++) { acc[b][0]=0.f; acc[b][1]=0.f; acc[b][2]=0.f; acc[b][3]=0.f; }
        if (Q < 192) {
            const float4* wp = (const float4*)Wv + (size_t)(k0 + kg * 16) * 192 + Q;
            #pragma unroll
            for (int kk = 0; kk < 16; kk++) {
                float4 w = wp[(size_t)kk * 192];
                int ki = kg * 16 + kk;
                #pragma unroll
                for (int b = 0; b < Bb; b++) {
                    float a = sa[b][ki];
                    acc[b][0] += a * w.x; acc[b][1] += a * w.y;
                    acc[b][2] += a * w.z; acc[b][3] += a * w.w;
                }
            }
        } else {
            const float4* wp = (const float4*)W1 + (size_t)(k0 + kg * 16) * 48 + (Q - 192);
            #pragma unroll
            for (int kk = 0; kk < 16; kk++) {
                float4 w = wp[(size_t)kk * 48];
                int ki = kg * 16 + kk;
                #pragma unroll
                for (int b = 0; b < Bb; b++) {
                    float a = sa[b][ki];
                    acc[b][0] += a * w.x; acc[b][1] += a * w.y;
                    acc[b][2] += a * w.z; acc[b][3] += a * w.w;
                }
            }
        }
        #pragma unroll
        for (int b = 0; b < Bb; b++)
            #pragma unroll
            for (int j = 0; j < 4; j++) {
                acc[b][j] += __shfl_xor_sync(0xffffffffu, acc[b][j], 1);
                acc[b][j] += __shfl_xor_sync(0xffffffffu, acc[b][j], 2);
            }
        if (kg == 0) {
            if (Q < 192) {
                #pragma unroll
                for (int b = 0; b < Bb; b++)
                    #pragma unroll
                    for (int j = 0; j < 4; j++)
                        atomicAdd(&g_scr[S_VB + b * Cdim + 4 * Q + j], acc[b][j]);
            } else {
                #pragma unroll
                for (int b = 0; b < Bb; b++)
                    #pragma unroll
                    for (int j = 0; j < 4; j++)
                        atomicAdd(&g_scr[S_H + b * CRdim + 4 * (Q - 192) + j], acc[b][j]);
            }
        }
    }

    grid_bar(0, 60);

    // ---------------- Stage B (blocks 0..11) ----------------
    if (blockIdx.x < 12) {
        int ct = blockIdx.x & 3;           // 0..3 (48-quad tile of 192)
        int kt = blockIdx.x >> 2;          // 0..2 (k tile of 64 over K=192)
        int k0 = kt * 64;
        for (int i = t; i < Bb * 64; i += 192) {
            int b = i >> 6, kk = i & 63;
            float v = g_scr[S_H + b * CRdim + k0 + kk] + b1[k0 + kk];
            sa[b][kk] = v > 0.f ? v : 0.f;
        }
        __syncthreads();
        int Q = ct * 48 + q;
        float acc[Bb][4];
        #pragma unroll
        for (int b = 0; b < Bb; b++) { acc[b][0]=0.f; acc[b][1]=0.f; acc[b][2]=0.f; acc[b][3]=0.f; }
        const float4* wp = (const float4*)W2 + (size_t)(k0 + kg * 16) * 192 + Q;
        #pragma unroll
        for (int kk = 0; kk < 16; kk++) {
            float4 w = wp[(size_t)kk * 192];
            int ki = kg * 16 + kk;
            #pragma unroll
            for (int b = 0; b < Bb; b++) {
                float a = sa[b][ki];
                acc[b][0] += a * w.x; acc[b][1] += a * w.y;
                acc[b][2] += a * w.z; acc[b][3] += a * w.w;
            }
        }
        #pragma unroll
        for (int b = 0; b < Bb; b++)
            #pragma unroll
            for (int j = 0; j < 4; j++) {
                acc[b][j] += __shfl_xor_sync(0xffffffffu, acc[b][j], 1);
                acc[b][j] += __shfl_xor_sync(0xffffffffu, acc[b][j], 2);
            }
        if (kg == 0) {
            #pragma unroll
            for (int b = 0; b < Bb; b++)
                #pragma unroll
                for (int j = 0; j < 4; j++)
                    atomicAdd(&g_scr[S_CA + b * Cdim + 4 * Q + j], acc[b][j]);
        }
    }

    grid_bar(1, 60);

    // ---------------- Stage C (blocks 0..47) ----------------
    if (blockIdx.x < 48) {
        int ct = blockIdx.x & 3;           // 0..3
        int kt = blockIdx.x >> 2;          // 0..11
        int k0 = kt * 64;
        for (int i = t; i < Bb * 64; i += 192) {
            int b = i >> 6, kk = i & 63;
            int k = k0 + kk;
            float vb = g_scr[S_VB + b * Cdim + k] + bv[k];
            float cp = g_scr[S_CA + b * Cdim + k] + b2[k];
            sa[b][kk] = vb * (1.f / (1.f + __expf(-cp)));
        }
        __syncthreads();
        int Q = ct * 48 + q;
        float acc[Bb][4];
        #pragma unroll
        for (int b = 0; b < Bb; b++) { acc[b][0]=0.f; acc[b][1]=0.f; acc[b][2]=0.f; acc[b][3]=0.f; }
        const float4* wp = (const float4*)Wo + (size_t)(k0 + kg * 16) * 192 + Q;
        #pragma unroll
        for (int kk = 0; kk < 16; kk++) {
            float4 w = wp[(size_t)kk * 192];
            int ki = kg * 16 + kk;
            #pragma unroll
            for (int b = 0; b < Bb; b++) {
                float a = sa[b][ki];
                acc[b][0] += a * w.x; acc[b][1] += a * w.y;
                acc[b][2] += a * w.z; acc[b][3] += a * w.w;
            }
        }
        #pragma unroll
        for (int b = 0; b < Bb; b++)
            #pragma unroll
            for (int j = 0; j < 4; j++) {
                acc[b][j] += __shfl_xor_sync(0xffffffffu, acc[b][j], 1);
                acc[b][j] += __shfl_xor_sync(0xffffffffu, acc[b][j], 2);
            }
        if (kg == 0) {
            #pragma unroll
            for (int b = 0; b < Bb; b++)
                #pragma unroll
                for (int j = 0; j < 4; j++)
                    atomicAdd(&g_scr[S_YB + b * Cdim + 4 * Q + j], acc[b][j]);
        }
    }
}

// ───────────────────────── K3: warp-per-row fused residual + LN ────────────
// 192 threads = 6 warps = 6 rows per block; pure shfl reduction, no bar.sync.
__global__ void __launch_bounds__(192) k_ln(const float* __restrict__ x,
                                            const float* __restrict__ bo,
                                            const float* __restrict__ gamma,
                                            const float* __restrict__ beta,
                                            float* __restrict__ out) {
    int row = blockIdx.x * 6 + (threadIdx.x >> 5);
    if (row >= Bb * Nn) return;
    int lane = threadIdx.x & 31;
    int b = row >> 10;
    const float4* xp = reinterpret_cast<const float4*>(x + (size_t)row * Cdim);
    const float4* yp = reinterpret_cast<const float4*>(&g_scr[S_YB + b * Cdim]);
    const float4* bp = reinterpret_cast<const float4*>(bo);
    float4 v[6];
    float s = 0.f, qs = 0.f;
    #pragma unroll
    for (int i = 0; i < 6; i++) {
        int c = lane + 32 * i;
        float4 xv = xp[c], yv = yp[c], b4 = bp[c];
        v[i].x = xv.x + yv.x + b4.x;
        v[i].y = xv.y + yv.y + b4.y;
        v[i].z = xv.z + yv.z + b4.z;
        v[i].w = xv.w + yv.w + b4.w;
        s  += v[i].x + v[i].y + v[i].z + v[i].w;
        qs += v[i].x*v[i].x + v[i].y*v[i].y + v[i].z*v[i].z + v[i].w*v[i].w;
    }
    #pragma unroll
    for (int o = 16; o; o >>= 1) {
        s  += __shfl_xor_sync(0xffffffffu, s, o);
        qs += __shfl_xor_sync(0xffffffffu, qs, o);
    }
    float mean = s * (1.0f / Cdim);
    float var = qs * (1.0f / Cdim) - mean * mean;
    float rstd = rsqrtf(var + 1e-5f);
    const float4* gp = reinterpret_cast<const float4*>(gamma);
    const float4* ep = reinterpret_cast<const float4*>(beta);
    float4* op = reinterpret_cast<float4*>(out + (size_t)row * Cdim);
    #pragma unroll
    for (int i = 0; i < 6; i++) {
        int c = lane + 32 * i;
        float4 g4 = gp[c], e4 = ep[c], o4;
        o4.x = (v[i].x - mean) * rstd * g4.x + e4.x;
        o4.y = (v[i].y - mean) * rstd * g4.y + e4.y;
        o4.z = (v[i].z - mean) * rstd * g4.z + e4.z;
        o4.w = (v[i].w - mean) * rstd * g4.w + e4.w;
        op[c] = o4;
    }
}

extern "C" void kernel_launch(void* const* d_in, const int* in_sizes, int n_in,
                              void* d_out, int out_size) {
    const float* x     = (const float*)d_in[0];
    // d_in[1..4] = Wq, bq, Wk, bk — mathematically unused: k is constant over
    // sequence positions, so softmax is exactly uniform and attention output
    // equals mean(v) = gc@Wv + bv, independent of q/k.
    const float* Wv    = (const float*)d_in[5];
    const float* bv    = (const float*)d_in[6];
    const float* W1    = (const float*)d_in[7];
    const float* b1    = (const float*)d_in[8];
    const float* W2    = (const float*)d_in[9];
    const float* b2    = (const float*)d_in[10];
    const float* Wo    = (const float*)d_in[11];
    const float* bo    = (const float*)d_in[12];
    const float* gamma = (const float*)d_in[13];
    const float* beta  = (const float*)d_in[14];
    float* out = (float*)d_out;

    k_gc<<<136, 192>>>(x);
    k_chain<<<60, 192>>>(Wv, W1, W2, Wo, bv, b1, b2);
    k_ln<<<(Bb * Nn + 5) / 6, 192>>>(x, bo, gamma, beta, out);
}

// round 6
// speedup vs baseline: 1.1284x; 1.0196x over previous
#include <cuda_runtime.h>

#define Cdim 768
#define CRdim 192
#define Bb 8
#define Nn 1024

// Scratch layout (floats): gc | vbar | ca | ybar | h
#define S_GC  0
#define S_VB  (Bb * Cdim)
#define S_CA  (2 * Bb * Cdim)
#define S_YB  (3 * Bb * Cdim)
#define S_H   (4 * Bb * Cdim)
#define S_ZERO_END (4 * Bb * Cdim + Bb * CRdim)
__device__ __align__(16) float g_scr[S_ZERO_END];
__device__ unsigned int g_bar[4];   // [0]=cnt0 [1]=flag0 [2]=cnt1 [3]=flag1

// ───────────────────────── K1: gc reduce + zero accumulators ───────────────
// blocks 0..511: each sums 16 rows of one batch, atomicAdd into gc (scaled).
//   INVARIANT: gc is zero on entry — restored by k_chain (blocks 48..59 zero
//   it right after its last use at grid_bar(0)), so every call is identical.
// blocks 512..519: zero the GEMM accumulators + barrier state (not gc!).
__global__ void __launch_bounds__(192) k_gc(const float* __restrict__ x) {
    int t = threadIdx.x;
    if (blockIdx.x < 512) {
        int b = blockIdx.x >> 6;           // batch
        int chunk = blockIdx.x & 63;       // 16-row chunk
        const float4* p = reinterpret_cast<const float4*>(x)
                        + (size_t)(b * Nn + chunk * 16) * (Cdim / 4) + t;
        float4 s = make_float4(0.f, 0.f, 0.f, 0.f);
        #pragma unroll
        for (int n = 0; n < 16; n++) {
            float4 v = p[(size_t)n * (Cdim / 4)];
            s.x += v.x; s.y += v.y; s.z += v.z; s.w += v.w;
        }
        float* g = &g_scr[S_GC + b * Cdim + 4 * t];
        const float inv = 1.0f / Nn;
        atomicAdd(g + 0, s.x * inv);
        atomicAdd(g + 1, s.y * inv);
        atomicAdd(g + 2, s.z * inv);
        atomicAdd(g + 3, s.w * inv);
    } else {
        int i = (blockIdx.x - 512) * 192 + t;
        for (; i < S_ZERO_END - S_VB; i += 8 * 192) g_scr[S_VB + i] = 0.f;
        if (blockIdx.x == 512 && t < 4) g_bar[t] = 0u;
    }
}

// ───────────────────────── grid barrier (all 60 blocks resident) ───────────
__device__ __forceinline__ void grid_bar(int slot, int nblocks) {
    __syncthreads();
    if (threadIdx.x == 0) {
        __threadfence();
        unsigned old = atomicAdd(&g_bar[2 * slot], 1u);
        if (old == (unsigned)(nblocks - 1)) {
            atomicExch(&g_bar[2 * slot + 1], 1u);
        } else {
            while (*((volatile unsigned int*)&g_bar[2 * slot + 1]) == 0u) { }
        }
        __threadfence();
    }
    __syncthreads();
}

// ───────────────────────── K2: fused GEMM chain ────────────────────────────
// grid 60 x 192 threads.  Thread = (quad q = t>>2, k-lane kg = t&3).
// Stage A (60 blk): vbar = gc@Wv, h = gc@W1        (atomic k-split partials)
// Stage B (12 blk): ca_pre = relu(h+b1)@W2 ; blocks 48..59 zero gc for the
//                   next call (gc fully consumed at grid_bar(0)).
// Stage C (48 blk): ybar = ((vbar+bv)*sigmoid(ca+b2))@Wo
__global__ void __launch_bounds__(192) k_chain(const float* __restrict__ Wv,
                                               const float* __restrict__ W1,
                                               const float* __restrict__ W2,
                                               const float* __restrict__ Wo,
                                               const float* __restrict__ bv,
                                               const float* __restrict__ b1,
                                               const float* __restrict__ b2) {
    __shared__ float sa[Bb][64];
    int t = threadIdx.x;
    int q = t >> 2, kg = t & 3;

    // ---------------- Stage A ----------------
    {
        int ct = blockIdx.x / 12;          // 0..4  (col tile of 48 quads)
        int kt = blockIdx.x % 12;          // 0..11 (k tile of 64)
        int k0 = kt * 64;
        for (int i = t; i < Bb * 64; i += 192) {
            int b = i >> 6, kk = i & 63;
            sa[b][kk] = g_scr[S_GC + b * Cdim + k0 + kk];
        }
        __syncthreads();
        int Q = ct * 48 + q;               // 0..239 col-quad
        float acc[Bb][4];
        #pragma unroll
        for (int b = 0; b < Bb; b++) { acc[b][0]=0.f; acc[b][1]=0.f; acc[b][2]=0.f; acc[b][3]=0.f; }
        if (Q < 192) {
            const float4* wp = (const float4*)Wv + (size_t)(k0 + kg * 16) * 192 + Q;
            #pragma unroll
            for (int kk = 0; kk < 16; kk++) {
                float4 w = wp[(size_t)kk * 192];
                int ki = kg * 16 + kk;
                #pragma unroll
                for (int b = 0; b < Bb; b++) {
                    float a = sa[b][ki];
                    acc[b][0] += a * w.x; acc[b][1] += a * w.y;
                    acc[b][2] += a * w.z; acc[b][3] += a * w.w;
                }
            }
        } else {
            const float4* wp = (const float4*)W1 + (size_t)(k0 + kg * 16) * 48 + (Q - 192);
            #pragma unroll
            for (int kk = 0; kk < 16; kk++) {
                float4 w = wp[(size_t)kk * 48];
                int ki = kg * 16 + kk;
                #pragma unroll
                for (int b = 0; b < Bb; b++) {
                    float a = sa[b][ki];
                    acc[b][0] += a * w.x; acc[b][1] += a * w.y;
                    acc[b][2] += a * w.z; acc[b][3] += a * w.w;
                }
            }
        }
        #pragma unroll
        for (int b = 0; b < Bb; b++)
            #pragma unroll
            for (int j = 0; j < 4; j++) {
                acc[b][j] += __shfl_xor_sync(0xffffffffu, acc[b][j], 1);
                acc[b][j] += __shfl_xor_sync(0xffffffffu, acc[b][j], 2);
            }
        if (kg == 0) {
            if (Q < 192) {
                #pragma unroll
                for (int b = 0; b < Bb; b++)
                    #pragma unroll
                    for (int j = 0; j < 4; j++)
                        atomicAdd(&g_scr[S_VB + b * Cdim + 4 * Q + j], acc[b][j]);
            } else {
                #pragma unroll
                for (int b = 0; b < Bb; b++)
                    #pragma unroll
                    for (int j = 0; j < 4; j++)
                        atomicAdd(&g_scr[S_H + b * CRdim + 4 * (Q - 192) + j], acc[b][j]);
            }
        }
    }

    grid_bar(0, 60);

    // ---------------- Stage B (blocks 0..11) + gc re-zero (48..59) ---------
    if (blockIdx.x < 12) {
        int ct = blockIdx.x & 3;           // 0..3 (48-quad tile of 192)
        int kt = blockIdx.x >> 2;          // 0..2 (k tile of 64 over K=192)
        int k0 = kt * 64;
        for (int i = t; i < Bb * 64; i += 192) {
            int b = i >> 6, kk = i & 63;
            float v = g_scr[S_H + b * CRdim + k0 + kk] + b1[k0 + kk];
            sa[b][kk] = v > 0.f ? v : 0.f;
        }
        __syncthreads();
        int Q = ct * 48 + q;
        float acc[Bb][4];
        #pragma unroll
        for (int b = 0; b < Bb; b++) { acc[b][0]=0.f; acc[b][1]=0.f; acc[b][2]=0.f; acc[b][3]=0.f; }
        const float4* wp = (const float4*)W2 + (size_t)(k0 + kg * 16) * 192 + Q;
        #pragma unroll
        for (int kk = 0; kk < 16; kk++) {
            float4 w = wp[(size_t)kk * 192];
            int ki = kg * 16 + kk;
            #pragma unroll
            for (int b = 0; b < Bb; b++) {
                float a = sa[b][ki];
                acc[b][0] += a * w.x; acc[b][1] += a * w.y;
                acc[b][2] += a * w.z; acc[b][3] += a * w.w;
            }
        }
        #pragma unroll
        for (int b = 0; b < Bb; b++)
            #pragma unroll
            for (int j = 0; j < 4; j++) {
                acc[b][j] += __shfl_xor_sync(0xffffffffu, acc[b][j], 1);
                acc[b][j] += __shfl_xor_sync(0xffffffffu, acc[b][j], 2);
            }
        if (kg == 0) {
            #pragma unroll
            for (int b = 0; b < Bb; b++)
                #pragma unroll
                for (int j = 0; j < 4; j++)
                    atomicAdd(&g_scr[S_CA + b * Cdim + 4 * Q + j], acc[b][j]);
        }
    } else if (blockIdx.x >= 48) {
        // gc's last read was Stage A (before grid_bar(0)); zero it here so the
        // next call's k_gc accumulates from zero. Restores the call invariant.
        for (int i = (blockIdx.x - 48) * 192 + t; i < Bb * Cdim; i += 12 * 192)
            g_scr[S_GC + i] = 0.f;
    }

    grid_bar(1, 60);

    // ---------------- Stage C (blocks 0..47) ----------------
    if (blockIdx.x < 48) {
        int ct = blockIdx.x & 3;           // 0..3
        int kt = blockIdx.x >> 2;          // 0..11
        int k0 = kt * 64;
        for (int i = t; i < Bb * 64; i += 192) {
            int b = i >> 6, kk = i & 63;
            int k = k0 + kk;
            float vb = g_scr[S_VB + b * Cdim + k] + bv[k];
            float cp = g_scr[S_CA + b * Cdim + k] + b2[k];
            sa[b][kk] = vb * (1.f / (1.f + __expf(-cp)));
        }
        __syncthreads();
        int Q = ct * 48 + q;
        float acc[Bb][4];
        #pragma unroll
        for (int b = 0; b < Bb; b++) { acc[b][0]=0.f; acc[b][1]=0.f; acc[b][2]=0.f; acc[b][3]=0.f; }
        const float4* wp = (const float4*)Wo + (size_t)(k0 + kg * 16) * 192 + Q;
        #pragma unroll
        for (int kk = 0; kk < 16; kk++) {
            float4 w = wp[(size_t)kk * 192];
            int ki = kg * 16 + kk;
            #pragma unroll
            for (int b = 0; b < Bb; b++) {
                float a = sa[b][ki];
                acc[b][0] += a * w.x; acc[b][1] += a * w.y;
                acc[b][2] += a * w.z; acc[b][3] += a * w.w;
            }
        }
        #pragma unroll
        for (int b = 0; b < Bb; b++)
            #pragma unroll
            for (int j = 0; j < 4; j++) {
                acc[b][j] += __shfl_xor_sync(0xffffffffu, acc[b][j], 1);
                acc[b][j] += __shfl_xor_sync(0xffffffffu, acc[b][j], 2);
            }
        if (kg == 0) {
            #pragma unroll
            for (int b = 0; b < Bb; b++)
                #pragma unroll
                for (int j = 0; j < 4; j++)
                    atomicAdd(&g_scr[S_YB + b * Cdim + 4 * Q + j], acc[b][j]);
        }
    }
}

// ───────────────────────── K3: warp-per-row fused residual + LN ────────────
__global__ void __launch_bounds__(192) k_ln(const float* __restrict__ x,
                                            const float* __restrict__ bo,
                                            const float* __restrict__ gamma,
                                            const float* __restrict__ beta,
                                            float* __restrict__ out) {
    int row = blockIdx.x * 6 + (threadIdx.x >> 5);
    if (row >= Bb * Nn) return;
    int lane = threadIdx.x & 31;
    int b = row >> 10;
    const float4* xp = reinterpret_cast<const float4*>(x + (size_t)row * Cdim);
    const float4* yp = reinterpret_cast<const float4*>(&g_scr[S_YB + b * Cdim]);
    const float4* bp = reinterpret_cast<const float4*>(bo);
    float4 v[6];
    float s = 0.f, qs = 0.f;
    #pragma unroll
    for (int i = 0; i < 6; i++) {
        int c = lane + 32 * i;
        float4 xv = xp[c], yv = yp[c], b4 = bp[c];
        v[i].x = xv.x + yv.x + b4.x;
        v[i].y = xv.y + yv.y + b4.y;
        v[i].z = xv.z + yv.z + b4.z;
        v[i].w = xv.w + yv.w + b4.w;
        s  += v[i].x + v[i].y + v[i].z + v[i].w;
        qs += v[i].x*v[i].x + v[i].y*v[i].y + v[i].z*v[i].z + v[i].w*v[i].w;
    }
    #pragma unroll
    for (int o = 16; o; o >>= 1) {
        s  += __shfl_xor_sync(0xffffffffu, s, o);
        qs += __shfl_xor_sync(0xffffffffu, qs, o);
    }
    float mean = s * (1.0f / Cdim);
    float var = qs * (1.0f / Cdim) - mean * mean;
    float rstd = rsqrtf(var + 1e-5f);
    const float4* gp = reinterpret_cast<const float4*>(gamma);
    const float4* ep = reinterpret_cast<const float4*>(beta);
    float4* op = reinterpret_cast<float4*>(out + (size_t)row * Cdim);
    #pragma unroll
    for (int i = 0; i < 6; i++) {
        int c = lane + 32 * i;
        float4 g4 = gp[c], e4 = ep[c], o4;
        o4.x = (v[i].x - mean) * rstd * g4.x + e4.x;
        o4.y = (v[i].y - mean) * rstd * g4.y + e4.y;
        o4.z = (v[i].z - mean) * rstd * g4.z + e4.z;
        o4.w = (v[i].w - mean) * rstd * g4.w + e4.w;
        op[c] = o4;
    }
}

extern "C" void kernel_launch(void* const* d_in, const int* in_sizes, int n_in,
                              void* d_out, int out_size) {
    const float* x     = (const float*)d_in[0];
    // d_in[1..4] = Wq, bq, Wk, bk — mathematically unused: k is constant over
    // sequence positions, so softmax is exactly uniform and attention output
    // equals mean(v) = gc@Wv + bv, independent of q/k.
    const float* Wv    = (const float*)d_in[5];
    const float* bv    = (const float*)d_in[6];
    const float* W1    = (const float*)d_in[7];
    const float* b1    = (const float*)d_in[8];
    const float* W2    = (const float*)d_in[9];
    const float* b2    = (const float*)d_in[10];
    const float* Wo    = (const float*)d_in[11];
    const float* bo    = (const float*)d_in[12];
    const float* gamma = (const float*)d_in[13];
    const float* beta  = (const float*)d_in[14];
    float* out = (float*)d_out;

    k_gc<<<520, 192>>>(x);
    k_chain<<<60, 192>>>(Wv, W1, W2, Wo, bv, b1, b2);
    k_ln<<<(Bb * Nn + 5) / 6, 192>>>(x, bo, gamma, beta, out);
}